// round 9
// baseline (speedup 1.0000x reference)
#include <cuda_runtime.h>
#include <cstdint>

#define PPN 100
#define THREADS 256

__device__ __forceinline__ uint32_t smem_u32(const void* p) {
    uint32_t a;
    asm("{ .reg .u64 t; cvta.to.shared.u64 t, %1; cvt.u32.u64 %0, t; }" : "=r"(a) : "l"(p));
    return a;
}
__device__ __forceinline__ void cp_async16(uint32_t saddr, const void* g) {
    asm volatile("cp.async.cg.shared.global [%0], [%1], 16;" :: "r"(saddr), "l"(g));
}
__device__ __forceinline__ void cp_commit() { asm volatile("cp.async.commit_group;"); }
__device__ __forceinline__ void cp_wait0()  { asm volatile("cp.async.wait_group 0;"); }

__device__ __forceinline__ void bulk_store(void* g, uint32_t saddr, uint32_t bytes) {
    asm volatile("cp.async.bulk.global.shared::cta.bulk_group [%0], [%1], %2;"
                 :: "l"(g), "r"(saddr), "r"(bytes) : "memory");
}
__device__ __forceinline__ void bulk_commit() {
    asm volatile("cp.async.bulk.commit_group;" ::: "memory");
}
__device__ __forceinline__ void bulk_wait_read0() {
    asm volatile("cp.async.bulk.wait_group.read 0;" ::: "memory");
}
__device__ __forceinline__ void fence_async_shared() {
    asm volatile("fence.proxy.async.shared::cta;" ::: "memory");
}

__global__ __launch_bounds__(THREADS, 4) void pfn_kernel(
    const float* __restrict__ px, const float* __restrict__ py,
    const float* __restrict__ pz, const float* __restrict__ pi,
    const int*   __restrict__ nv,
    const float* __restrict__ xs, const float* __restrict__ ys,
    const float* __restrict__ W,  const float* __restrict__ gamma,
    const float* __restrict__ beta, const float* __restrict__ bmean,
    const float* __restrict__ bvar,
    float* __restrict__ out, int P)
{
    __shared__ __align__(16) float sdata[2][6][PPN];
    __shared__ __align__(16) float sout[PPN * 64];   // 25.6 KB staging for one pillar
    // [0]=wx [1]=wy [2]=wz [3]=wi [4]=wxs [5]=wys [6..8]=mean-weights [9]=bias
    __shared__ float sW[10][32];
    __shared__ float ssum[3];
    __shared__ float pmax[32][33];
    __shared__ float bmax[32];

    const int tid  = threadIdx.x;
    const int wid  = tid >> 5, lane = tid & 31;
    const int stride = gridDim.x;

    // ---- fold BN + feature algebra into weights (once per CTA) ----
    if (tid < 32) {
        const float* Wr = W + tid * 9;
        float w0 = Wr[0], w1 = Wr[1], w2 = Wr[2], w3 = Wr[3];
        float w4 = Wr[4], w5 = Wr[5], w6 = Wr[6], w7 = Wr[7], w8 = Wr[8];
        float s = rsqrtf(bvar[tid] + 1e-3f) * gamma[tid];
        sW[0][tid] = (w0 + w4 + w7) * s;
        sW[1][tid] = (w1 + w5 + w8) * s;
        sW[2][tid] = (w2 + w6) * s;
        sW[3][tid] = w3 * s;
        sW[4][tid] = -w7 * s;
        sW[5][tid] = -w8 * s;
        sW[6][tid] = w4 * s;
        sW[7][tid] = w5 * s;
        sW[8][tid] = w6 * s;
        sW[9][tid] = beta[tid] - bmean[tid] * s;
    }

    // staging roles: 150 threads move one float4 each
    const int a = tid / 25, j = tid % 25;
    const float* src = (a == 0) ? px : (a == 1) ? py : (a == 2) ? pz
                     : (a == 3) ? pi : (a == 4) ? xs : ys;

    const int pid0 = blockIdx.x;

    if (pid0 < P && tid < 150) {
        cp_async16(smem_u32(&sdata[0][a][j * 4]), src + (size_t)pid0 * PPN + j * 4);
        cp_commit();
    }
    int nvp = (pid0 < P) ? __ldg(nv + pid0) : 1;
    cp_wait0();
    __syncthreads();

    const int q  = tid & 7;    // channel quad
    const int ng = tid >> 3;   // point group
    const int u0 = q * 4;

    // static (per-CTA) weight micro-tile, all in registers (R4 layout)
    float wx[4], wy[4], wz[4], wi[4], wxs[4], wys[4], b[4], km[3][4];
    #pragma unroll
    for (int t = 0; t < 4; t++) {
        const int u = u0 + t;
        wx[t]  = sW[0][u]; wy[t]  = sW[1][u]; wz[t] = sW[2][u];
        wi[t]  = sW[3][u]; wxs[t] = sW[4][u]; wys[t] = sW[5][u];
        km[0][t] = sW[6][u]; km[1][t] = sW[7][u]; km[2][t] = sW[8][u];
        b[t]   = sW[9][u];
    }

    float4* sout4 = (float4*)sout;                  // 16 float4 per point
    const uint32_t sout_addr = smem_u32(sout);

    int buf = 0;
    for (int pp = pid0; pp < P; pp += stride) {
        const int nxt = pp + stride;

        // prefetch next pillar's inputs (async, overlaps everything)
        if (nxt < P && tid < 150) {
            cp_async16(smem_u32(&sdata[buf ^ 1][a][j * 4]),
                       src + (size_t)nxt * PPN + j * 4);
            cp_commit();
        }
        const int nv_next = (nxt < P) ? __ldg(nv + nxt) : 1;

        // ---- points_mean over ALL N slots ----
        if (wid < 3) {
            const float* arr = sdata[buf][wid];
            float s = 0.f;
            #pragma unroll
            for (int n = lane; n < PPN; n += 32) s += arr[n];
            #pragma unroll
            for (int o = 16; o; o >>= 1) s += __shfl_down_sync(0xffffffffu, s, o);
            if (lane == 0) ssum[wid] = s;
        }
        // previous pillar's bulk store must have READ sout before we overwrite
        bulk_wait_read0();
        __syncthreads();

        const float fnv = (float)nvp;
        const float mx = ssum[0] / fnv, my = ssum[1] / fnv, mz = ssum[2] / fnv;

        float K[4];
        #pragma unroll
        for (int t = 0; t < 4; t++)
            K[t] = -(mx * km[0][t] + my * km[1][t] + mz * km[2][t]);

        float vmax[4] = {0.f, 0.f, 0.f, 0.f};   // post-ReLU >= 0

        #pragma unroll
        for (int base = 0; base < PPN; base += 32) {
            const int n = base + ng;
            if (n < PPN) {
                const float x  = sdata[buf][0][n], y  = sdata[buf][1][n];
                const float z  = sdata[buf][2][n], it = sdata[buf][3][n];
                const float xv = sdata[buf][4][n], yv = sdata[buf][5][n];
                const float m  = (n < nvp) ? 1.f : 0.f;

                float r[4];
                #pragma unroll
                for (int t = 0; t < 4; t++) {
                    float acc = K[t];
                    acc = fmaf(x,  wx[t],  acc);
                    acc = fmaf(y,  wy[t],  acc);
                    acc = fmaf(z,  wz[t],  acc);
                    acc = fmaf(it, wi[t],  acc);
                    acc = fmaf(xv, wxs[t], acc);
                    acc = fmaf(yv, wys[t], acc);
                    r[t] = fmaxf(fmaf(m, acc, b[t]), 0.f);
                    vmax[t] = fmaxf(vmax[t], r[t]);
                }
                float4 v; v.x = r[0]; v.y = r[1]; v.z = r[2]; v.w = r[3];
                sout4[n * 16 + q] = v;                       // channels [0,32)
            }
        }

        #pragma unroll
        for (int t = 0; t < 4; t++) pmax[ng][u0 + t] = vmax[t];
        __syncthreads();

        if (tid < 32) {
            float v0 = pmax[0][tid], v1 = pmax[1][tid];
            float v2 = pmax[2][tid], v3 = pmax[3][tid];
            #pragma unroll
            for (int r2 = 4; r2 < 32; r2 += 4) {
                v0 = fmaxf(v0, pmax[r2    ][tid]);
                v1 = fmaxf(v1, pmax[r2 + 1][tid]);
                v2 = fmaxf(v2, pmax[r2 + 2][tid]);
                v3 = fmaxf(v3, pmax[r2 + 3][tid]);
            }
            bmax[tid] = fmaxf(fmaxf(v0, v1), fmaxf(v2, v3));
        }
        __syncthreads();

        float4 bc;
        bc.x = bmax[u0 + 0]; bc.y = bmax[u0 + 1];
        bc.z = bmax[u0 + 2]; bc.w = bmax[u0 + 3];
        #pragma unroll
        for (int base = 0; base < PPN; base += 32) {
            const int n = base + ng;
            if (n < PPN) sout4[n * 16 + 8 + q] = bc;         // channels [32,64)
        }
        __syncthreads();                 // sout fully written

        // one bulk store for the whole pillar (off the L1/STG path)
        if (tid == 0) {
            fence_async_shared();
            bulk_store(out + (size_t)pp * PPN * 64, sout_addr, PPN * 64 * 4);
            bulk_commit();
        }

        nvp = nv_next;
        cp_wait0();                      // next input buffer staged
        __syncthreads();
        buf ^= 1;
    }
    // pending bulk group completes before grid end (async-proxy flush at exit)
}

extern "C" void kernel_launch(void* const* d_in, const int* in_sizes, int n_in,
                              void* d_out, int out_size)
{
    const float* px    = (const float*)d_in[0];
    const float* py    = (const float*)d_in[1];
    const float* pz    = (const float*)d_in[2];
    const float* pi    = (const float*)d_in[3];
    const int*   nv    = (const int*  )d_in[4];
    const float* xs    = (const float*)d_in[5];
    const float* ys    = (const float*)d_in[6];
    // d_in[7] = mask : derivable from num_voxels, not read
    const float* W     = (const float*)d_in[8];
    const float* gamma = (const float*)d_in[9];
    const float* beta  = (const float*)d_in[10];
    const float* bmean = (const float*)d_in[11];
    const float* bvar  = (const float*)d_in[12];

    const int P = in_sizes[4];
    int ctas = 148 * 4;
    if (ctas > P) ctas = P;
    pfn_kernel<<<ctas, THREADS>>>(px, py, pz, pi, nv, xs, ys,
                                  W, gamma, beta, bmean, bvar, (float*)d_out, P);
}

// round 10
// speedup vs baseline: 1.2784x; 1.2784x over previous
#include <cuda_runtime.h>
#include <cstdint>

#define PPN 100
#define THREADS 256

__device__ __forceinline__ uint32_t smem_u32(const void* p) {
    uint32_t a;
    asm("{ .reg .u64 t; cvta.to.shared.u64 t, %1; cvt.u32.u64 %0, t; }" : "=r"(a) : "l"(p));
    return a;
}
__device__ __forceinline__ void cp_async16(uint32_t saddr, const void* g) {
    asm volatile("cp.async.cg.shared.global [%0], [%1], 16;" :: "r"(saddr), "l"(g));
}
__device__ __forceinline__ void cp_commit() { asm volatile("cp.async.commit_group;"); }
__device__ __forceinline__ void cp_wait0()  { asm volatile("cp.async.wait_group 0;"); }

__global__ __launch_bounds__(THREADS, 4) void pfn_kernel(
    const float* __restrict__ px, const float* __restrict__ py,
    const float* __restrict__ pz, const float* __restrict__ pi,
    const int*   __restrict__ nv,
    const float* __restrict__ xs, const float* __restrict__ ys,
    const float* __restrict__ W,  const float* __restrict__ gamma,
    const float* __restrict__ beta, const float* __restrict__ bmean,
    const float* __restrict__ bvar,
    float* __restrict__ out, int P)
{
    // [buf][pillar][array][n]
    __shared__ __align__(16) float sdata[2][2][6][PPN];
    // [0]=wx [1]=wy [2]=wz [3]=wi [4]=wxs [5]=wys [6..8]=mean-weights [9]=bias
    __shared__ float sW[10][32];
    __shared__ float ssum[2][3];                 // [pillar][axis]
    __shared__ float pmax2[2][32][33];           // [pillar][ng][ch]
    __shared__ float bmax2[2][32];

    const int tid  = threadIdx.x;
    const int wid  = tid >> 5, lane = tid & 31;
    const int stride2 = gridDim.x * 2;           // pillars advance in pairs

    // ---- fold BN + feature algebra into weights (once per CTA) ----
    if (tid < 32) {
        const float* Wr = W + tid * 9;
        float w0 = Wr[0], w1 = Wr[1], w2 = Wr[2], w3 = Wr[3];
        float w4 = Wr[4], w5 = Wr[5], w6 = Wr[6], w7 = Wr[7], w8 = Wr[8];
        float s = rsqrtf(bvar[tid] + 1e-3f) * gamma[tid];
        sW[0][tid] = (w0 + w4 + w7) * s;
        sW[1][tid] = (w1 + w5 + w8) * s;
        sW[2][tid] = (w2 + w6) * s;
        sW[3][tid] = w3 * s;
        sW[4][tid] = -w7 * s;
        sW[5][tid] = -w8 * s;
        sW[6][tid] = w4 * s;
        sW[7][tid] = w5 * s;
        sW[8][tid] = w6 * s;
        sW[9][tid] = beta[tid] - bmean[tid] * s;
    }

    // staging: 300 float4 slots per pair; slot -> (pillar, array, j)
    // thread tid covers slot tid, and slot tid+256 when tid<44
    const int s0_pl = tid / 150, s0_r = tid % 150;
    const int s0_a = s0_r / 25,  s0_j = s0_r % 25;
    const int s1 = tid + 256;                    // < 300 only when tid < 44
    const int s1_pl = s1 / 150,  s1_r = s1 % 150;
    const int s1_a = s1_r / 25,  s1_j = s1_r % 25;

    const float* const srcs[6] = { px, py, pz, pi, xs, ys };
    const float* src0 = srcs[s0_a];
    const float* src1 = srcs[s1_a < 6 ? s1_a : 0];

    const int pid0 = blockIdx.x * 2;

    // ---- prologue: stage pair 0 into buffer 0 ----
    {
        const int pA = pid0, pB = pid0 + 1;
        if (s0_pl == 0 ? (pA < P) : (pB < P))
            cp_async16(smem_u32(&sdata[0][s0_pl][s0_a][s0_j * 4]),
                       src0 + (size_t)(s0_pl == 0 ? pA : pB) * PPN + s0_j * 4);
        if (tid < 44 && (s1_pl == 0 ? (pA < P) : (pB < P)))
            cp_async16(smem_u32(&sdata[0][s1_pl][s1_a][s1_j * 4]),
                       src1 + (size_t)(s1_pl == 0 ? pA : pB) * PPN + s1_j * 4);
        cp_commit();
    }
    int nvA = (pid0     < P) ? __ldg(nv + pid0)     : 1;
    int nvB = (pid0 + 1 < P) ? __ldg(nv + pid0 + 1) : 1;
    cp_wait0();
    __syncthreads();

    const int q  = tid & 7;    // channel quad
    const int ng = tid >> 3;   // point group
    const int u0 = q * 4;

    // static weight micro-tile (per-point weights in regs; km/b read per pillar)
    float wx[4], wy[4], wz[4], wi[4], wxs[4], wys[4];
    #pragma unroll
    for (int t = 0; t < 4; t++) {
        const int u = u0 + t;
        wx[t]  = sW[0][u]; wy[t]  = sW[1][u]; wz[t] = sW[2][u];
        wi[t]  = sW[3][u]; wxs[t] = sW[4][u]; wys[t] = sW[5][u];
    }

    int buf = 0;
    for (int pp = pid0; pp < P; pp += stride2) {
        const int nxtA = pp + stride2, nxtB = nxtA + 1;

        // ---- prefetch next pair into the other buffer ----
        if (nxtA < P) {
            if (s0_pl == 0 ? true : (nxtB < P))
                cp_async16(smem_u32(&sdata[buf ^ 1][s0_pl][s0_a][s0_j * 4]),
                           src0 + (size_t)(s0_pl == 0 ? nxtA : nxtB) * PPN + s0_j * 4);
            if (tid < 44 && (s1_pl == 0 ? true : (nxtB < P)))
                cp_async16(smem_u32(&sdata[buf ^ 1][s1_pl][s1_a][s1_j * 4]),
                           src1 + (size_t)(s1_pl == 0 ? nxtA : nxtB) * PPN + s1_j * 4);
            cp_commit();
        }
        const int nvA_n = (nxtA < P) ? __ldg(nv + nxtA) : 1;
        const int nvB_n = (nxtB < P) ? __ldg(nv + nxtB) : 1;

        // ---- means: warps 0-2 pillar A, warps 3-5 pillar B, one barrier ----
        if (wid < 6) {
            const int pl = wid / 3, ax = wid % 3;
            const float* arr = sdata[buf][pl][ax];
            float s = 0.f;
            #pragma unroll
            for (int n = lane; n < PPN; n += 32) s += arr[n];
            #pragma unroll
            for (int o = 16; o; o >>= 1) s += __shfl_down_sync(0xffffffffu, s, o);
            if (lane == 0) ssum[pl][ax] = s;
        }
        __syncthreads();

        const bool hasB = (pp + 1) < P;

        // ---- compute + store, pillar A then pillar B (sequential, shared regs) ----
        #pragma unroll
        for (int pl = 0; pl < 2; pl++) {
            if (pl == 1 && !hasB) break;
            const int   nvp = pl ? nvB : nvA;
            const float fnv = (float)nvp;
            const float mx = ssum[pl][0] / fnv;
            const float my = ssum[pl][1] / fnv;
            const float mz = ssum[pl][2] / fnv;

            float K[4], b[4];
            #pragma unroll
            for (int t = 0; t < 4; t++) {
                const int u = u0 + t;
                K[t] = -(mx * sW[6][u] + my * sW[7][u] + mz * sW[8][u]);
                b[t] = sW[9][u];
            }

            float vmax[4] = {0.f, 0.f, 0.f, 0.f};   // post-ReLU >= 0
            float4* out4 = (float4*)(out + (size_t)(pp + pl) * PPN * 64);
            const float (*sd)[PPN] = sdata[buf][pl];

            #pragma unroll
            for (int base = 0; base < PPN; base += 32) {
                const int n = base + ng;
                if (n < PPN) {
                    const float x  = sd[0][n], y  = sd[1][n];
                    const float z  = sd[2][n], it = sd[3][n];
                    const float xv = sd[4][n], yv = sd[5][n];
                    const float m  = (n < nvp) ? 1.f : 0.f;

                    float r[4];
                    #pragma unroll
                    for (int t = 0; t < 4; t++) {
                        float acc = K[t];
                        acc = fmaf(x,  wx[t],  acc);
                        acc = fmaf(y,  wy[t],  acc);
                        acc = fmaf(z,  wz[t],  acc);
                        acc = fmaf(it, wi[t],  acc);
                        acc = fmaf(xv, wxs[t], acc);
                        acc = fmaf(yv, wys[t], acc);
                        r[t] = fmaxf(fmaf(m, acc, b[t]), 0.f);
                        vmax[t] = fmaxf(vmax[t], r[t]);
                    }
                    float4 v; v.x = r[0]; v.y = r[1]; v.z = r[2]; v.w = r[3];
                    __stcs(&out4[(size_t)n * 16 + q], v);    // channels [0,32)
                }
            }
            #pragma unroll
            for (int t = 0; t < 4; t++) pmax2[pl][ng][u0 + t] = vmax[t];
        }
        __syncthreads();

        // ---- max reduce: warp 0 -> pillar A, warp 1 -> pillar B ----
        if (wid < 2 && (wid == 0 || hasB)) {
            float v0 = pmax2[wid][0][lane], v1 = pmax2[wid][1][lane];
            float v2 = pmax2[wid][2][lane], v3 = pmax2[wid][3][lane];
            #pragma unroll
            for (int r2 = 4; r2 < 32; r2 += 4) {
                v0 = fmaxf(v0, pmax2[wid][r2    ][lane]);
                v1 = fmaxf(v1, pmax2[wid][r2 + 1][lane]);
                v2 = fmaxf(v2, pmax2[wid][r2 + 2][lane]);
                v3 = fmaxf(v3, pmax2[wid][r2 + 3][lane]);
            }
            bmax2[wid][lane] = fmaxf(fmaxf(v0, v1), fmaxf(v2, v3));
        }
        __syncthreads();

        // ---- broadcast halves for both pillars ----
        #pragma unroll
        for (int pl = 0; pl < 2; pl++) {
            if (pl == 1 && !hasB) break;
            float4 bc;
            bc.x = bmax2[pl][u0 + 0]; bc.y = bmax2[pl][u0 + 1];
            bc.z = bmax2[pl][u0 + 2]; bc.w = bmax2[pl][u0 + 3];
            float4* out4 = (float4*)(out + (size_t)(pp + pl) * PPN * 64);
            #pragma unroll
            for (int base = 0; base < PPN; base += 32) {
                const int n = base + ng;
                if (n < PPN) __stcs(&out4[(size_t)n * 16 + 8 + q], bc);  // [32,64)
            }
        }

        nvA = nvA_n; nvB = nvB_n;
        cp_wait0();
        __syncthreads();
        buf ^= 1;
    }
}

extern "C" void kernel_launch(void* const* d_in, const int* in_sizes, int n_in,
                              void* d_out, int out_size)
{
    const float* px    = (const float*)d_in[0];
    const float* py    = (const float*)d_in[1];
    const float* pz    = (const float*)d_in[2];
    const float* pi    = (const float*)d_in[3];
    const int*   nv    = (const int*  )d_in[4];
    const float* xs    = (const float*)d_in[5];
    const float* ys    = (const float*)d_in[6];
    // d_in[7] = mask : derivable from num_voxels, not read
    const float* W     = (const float*)d_in[8];
    const float* gamma = (const float*)d_in[9];
    const float* beta  = (const float*)d_in[10];
    const float* bmean = (const float*)d_in[11];
    const float* bvar  = (const float*)d_in[12];

    const int P = in_sizes[4];
    int ctas = 148 * 4;
    if (ctas > (P + 1) / 2) ctas = (P + 1) / 2;
    pfn_kernel<<<ctas, THREADS>>>(px, py, pz, pi, nv, xs, ys,
                                  W, gamma, beta, bmean, bvar, (float*)d_out, P);
}